// round 8
// baseline (speedup 1.0000x reference)
#include <cuda_runtime.h>
#include <math.h>

#define D   32
#define HH  64
#define BB  8192
#define TT  256
#define MT  64      // rows per CTA; 128 CTAs
// 256 threads = 8 warps. Warp w: wx=w&1 (32-col half), wy=w>>1 (16-row block).
// Lane: tx=lane&7 (4 cols), tyl=lane>>3 (4 rows). Warp tile 16 rows x 32 cols.

// smem float offsets
#define O_W1D 0              // 33*128 dup'd swizzled
#define O_W2D 4224           // 64*128 dup'd swizzled
#define O_W3D 12416          // 64*64 dup'd
#define O_B1D 16512          // 128 dup'd
#define O_B2D 16640          // 128 dup'd
#define O_B3D 16768          // 64 dup'd
#define O_STD 16832          // 32
#define O_TS  16864          // 256
#define O_Z   17120          // 32*68 feature-major padded
#define O_H1  19296          // 64*68
#define O_H2  23648          // 64*68
#define SMEM_FLOATS 28000

typedef unsigned long long u64;

__device__ __forceinline__ u64 ffma2(u64 a, u64 b, u64 c) {
    u64 d; asm("fma.rn.f32x2 %0, %1, %2, %3;" : "=l"(d) : "l"(a), "l"(b), "l"(c)); return d;
}
__device__ __forceinline__ u64 fmul2(u64 a, u64 b) {
    u64 d; asm("mul.rn.f32x2 %0, %1, %2;" : "=l"(d) : "l"(a), "l"(b)); return d;
}
__device__ __forceinline__ u64 pk(float x, float y) {
    u64 r; asm("mov.b64 %0, {%1, %2};" : "=l"(r) : "f"(x), "f"(y)); return r;
}
__device__ __forceinline__ float2 unpk(u64 v) {
    float2 r; asm("mov.b64 {%0, %1}, %2;" : "=f"(r.x), "=f"(r.y) : "l"(v)); return r;
}
__device__ __forceinline__ float tanha(float x) {
    float y; asm("tanh.approx.f32 %0, %1;" : "=f"(y) : "f"(x)); return y;
}

union F4U { float4 f; u64 u[2]; };
__device__ __forceinline__ F4U ld4(const float* p) { F4U r; r.f = *(const float4*)p; return r; }

__global__ __launch_bounds__(256, 1)
void sde_kernel(const float* __restrict__ z0,
                const float* __restrict__ ts,
                const float* __restrict__ dW,
                const float* __restrict__ W1, const float* __restrict__ b1,
                const float* __restrict__ W2, const float* __restrict__ b2,
                const float* __restrict__ W3, const float* __restrict__ b3,
                const float* __restrict__ logstd,
                float* __restrict__ out)
{
    extern __shared__ float sm[];
    float* sW1d = sm + O_W1D;
    float* sW2d = sm + O_W2D;
    float* sW3d = sm + O_W3D;
    float* sb1d = sm + O_B1D;
    float* sb2d = sm + O_B2D;
    float* sb3d = sm + O_B3D;
    float* sstd = sm + O_STD;
    float* sTs  = sm + O_TS;
    float* sZ   = sm + O_Z;
    float* sH1  = sm + O_H1;
    float* sH2  = sm + O_H2;

    const int tid  = threadIdx.x;
    const int w    = tid >> 5;
    const int lane = tid & 31;
    const int tx   = lane & 7;
    const int tyl  = lane >> 3;
    const int wx   = w & 1;
    const int wy   = w >> 1;
    const int m0   = wy * 16 + tyl * 4;      // 4 rows per thread
    const int j0   = wx * 32 + tx * 4;       // 4 cols (GEMM1/2)
    const int d0   = wx * 16 + tx * 2;       // 2 cols (GEMM3 / z)
    const int base = blockIdx.x * MT;

    // ---- staging: weights duplicated ({w,w} adjacent); W1/W2 16B-unit swizzled ----
    for (int i = tid; i < 33 * 128; i += 256) {
        int row = i >> 7, f = i & 127;
        int u = f >> 2, us = u ^ ((u >> 3) & 1);
        sW1d[(row << 7) + (us << 2) + (f & 3)] = W1[(row << 6) + (f >> 1)];
    }
    for (int i = tid; i < 64 * 128; i += 256) {
        int row = i >> 7, f = i & 127;
        int u = f >> 2, us = u ^ ((u >> 3) & 1);
        sW2d[(row << 7) + (us << 2) + (f & 3)] = W2[(row << 6) + (f >> 1)];
    }
    for (int i = tid; i < 64 * 64; i += 256) {
        int row = i >> 6, f = i & 63;
        sW3d[(row << 6) + f] = W3[(row << 5) + (f >> 1)];
    }
    if (tid < 128) { sb1d[tid] = b1[tid >> 1]; sb2d[tid] = b2[tid >> 1]; }
    if (tid < 64)  { sb3d[tid] = b3[tid >> 1]; }
    if (tid < 32)  { sstd[tid] = expf(logstd[tid]); }
    sTs[tid] = ts[tid];
    __syncthreads();

    // ---- hoisted per-thread constants & offsets ----
    // FIX vs R6: unit index of first dup'd col-pair is j0/2 = wx*16 + tx*2
    const int u0  = wx * 16 + tx * 2;
    const int uu0 = (u0 ^ ((u0 >> 3) & 1)) << 2;
    const int u1  = u0 + 1;
    const int uu1 = (u1 ^ ((u1 >> 3) & 1)) << 2;
    const int obw3 = 2 * d0;                          // W3 dup'd float offset

    u64 bc1[4], bc2[4], bc3[2], w1t[4];
    {
        F4U t;
        t = ld4(sb1d + 2 * j0);     bc1[0] = t.u[0]; bc1[1] = t.u[1];
        t = ld4(sb1d + 2 * j0 + 4); bc1[2] = t.u[0]; bc1[3] = t.u[1];
        t = ld4(sb2d + 2 * j0);     bc2[0] = t.u[0]; bc2[1] = t.u[1];
        t = ld4(sb2d + 2 * j0 + 4); bc2[2] = t.u[0]; bc2[3] = t.u[1];
        t = ld4(sb3d + 2 * d0);     bc3[0] = t.u[0]; bc3[1] = t.u[1];
        t = ld4(sW1d + uu0);        w1t[0] = t.u[0]; w1t[1] = t.u[1];
        t = ld4(sW1d + uu1);        w1t[2] = t.u[0]; w1t[3] = t.u[1];
    }
    const u64 s2base = pk(sstd[d0], sstd[d0 + 1]);

    // ---- z init: registers (col-packed per row), out[0], padded feature-major sZ ----
    u64 zp[4];
    #pragma unroll
    for (int r = 0; r < 4; r++) {
        zp[r] = *(const u64*)&z0[(size_t)(base + m0 + r) * D + d0];
        *(u64*)&out[(size_t)(base + m0 + r) * D + d0] = zp[r];
    }
    #pragma unroll
    for (int c = 0; c < 2; c++) {
        float4 v;
        if (c == 0) { v.x = unpk(zp[0]).x; v.y = unpk(zp[1]).x; v.z = unpk(zp[2]).x; v.w = unpk(zp[3]).x; }
        else        { v.x = unpk(zp[0]).y; v.y = unpk(zp[1]).y; v.z = unpk(zp[2]).y; v.w = unpk(zp[3]).y; }
        *(float4*)(sZ + (d0 + c) * 68 + m0) = v;
    }
    __syncthreads();

    // ==================== time loop ====================
    for (int t = 0; t < TT - 1; ++t) {
        const float tcur = sTs[t];
        const float dtv  = sTs[t + 1] - tcur;
        const float sq   = sqrtf(dtv);

        // prefetch noise (consumed in epilogue3)
        u64 dwv[4];
        {
            const float* dwp = dW + ((size_t)t * BB + base + m0) * D + d0;
            #pragma unroll
            for (int r = 0; r < 4; r++) dwv[r] = *(const u64*)(dwp + (size_t)r * D);
        }

        u64 acc[2][4];

        // ---------- GEMM1: [t,z] @ W1 ----------
        {
            u64 t2 = pk(tcur, tcur);
            #pragma unroll
            for (int c = 0; c < 4; c++) {
                u64 ic = ffma2(t2, w1t[c], bc1[c]);
                acc[0][c] = ic; acc[1][c] = ic;
            }
            #pragma unroll 8
            for (int k = 0; k < D; ++k) {
                F4U a  = ld4(sZ + k * 68 + m0);
                F4U b0 = ld4(sW1d + (k + 1) * 128 + uu0);
                F4U b1v = ld4(sW1d + (k + 1) * 128 + uu1);
                #pragma unroll
                for (int c = 0; c < 4; c++) {
                    u64 bv = (c < 2) ? b0.u[c] : b1v.u[c - 2];
                    acc[0][c] = ffma2(a.u[0], bv, acc[0][c]);
                    acc[1][c] = ffma2(a.u[1], bv, acc[1][c]);
                }
            }
            #pragma unroll
            for (int c = 0; c < 4; c++) {
                float2 r0 = unpk(acc[0][c]), r1 = unpk(acc[1][c]);
                float4 v;
                v.x = tanha(r0.x); v.y = tanha(r0.y); v.z = tanha(r1.x); v.w = tanha(r1.y);
                *(float4*)(sH1 + (j0 + c) * 68 + m0) = v;
            }
        }
        __syncthreads();

        // ---------- GEMM2: h1 @ W2 ----------
        {
            #pragma unroll
            for (int c = 0; c < 4; c++) { acc[0][c] = bc2[c]; acc[1][c] = bc2[c]; }
            #pragma unroll 8
            for (int k = 0; k < HH; ++k) {
                F4U a  = ld4(sH1 + k * 68 + m0);
                F4U b0 = ld4(sW2d + k * 128 + uu0);
                F4U b1v = ld4(sW2d + k * 128 + uu1);
                #pragma unroll
                for (int c = 0; c < 4; c++) {
                    u64 bv = (c < 2) ? b0.u[c] : b1v.u[c - 2];
                    acc[0][c] = ffma2(a.u[0], bv, acc[0][c]);
                    acc[1][c] = ffma2(a.u[1], bv, acc[1][c]);
                }
            }
            #pragma unroll
            for (int c = 0; c < 4; c++) {
                float2 r0 = unpk(acc[0][c]), r1 = unpk(acc[1][c]);
                float4 v;
                v.x = tanha(r0.x); v.y = tanha(r0.y); v.z = tanha(r1.x); v.w = tanha(r1.y);
                *(float4*)(sH2 + (j0 + c) * 68 + m0) = v;
            }
        }
        __syncthreads();

        // ---------- GEMM3: h2 @ W3 + Euler-Maruyama ----------
        {
            u64 a3[2][2];
            a3[0][0] = bc3[0]; a3[0][1] = bc3[1];
            a3[1][0] = bc3[0]; a3[1][1] = bc3[1];
            #pragma unroll 8
            for (int k = 0; k < HH; ++k) {
                F4U a = ld4(sH2 + k * 68 + m0);
                F4U b = ld4(sW3d + k * 64 + obw3);
                a3[0][0] = ffma2(a.u[0], b.u[0], a3[0][0]);
                a3[0][1] = ffma2(a.u[0], b.u[1], a3[0][1]);
                a3[1][0] = ffma2(a.u[1], b.u[0], a3[1][0]);
                a3[1][1] = ffma2(a.u[1], b.u[1], a3[1][1]);
            }

            const u64 dt2 = pk(dtv, dtv);
            const u64 s2  = fmul2(s2base, pk(sq, sq));
            float* orow = out + ((size_t)(t + 1) * BB + base + m0) * D + d0;
            #pragma unroll
            for (int r = 0; r < 4; r++) {
                float2 c0 = unpk(a3[r >> 1][0]);
                float2 c1 = unpk(a3[r >> 1][1]);
                u64 fe = (r & 1) ? pk(c0.y, c1.y) : pk(c0.x, c1.x);
                zp[r] = ffma2(fe, dt2, ffma2(s2, dwv[r], zp[r]));
                *(u64*)(orow + (size_t)r * D) = zp[r];
            }
            #pragma unroll
            for (int c = 0; c < 2; c++) {
                float4 v;
                if (c == 0) { v.x = unpk(zp[0]).x; v.y = unpk(zp[1]).x; v.z = unpk(zp[2]).x; v.w = unpk(zp[3]).x; }
                else        { v.x = unpk(zp[0]).y; v.y = unpk(zp[1]).y; v.z = unpk(zp[2]).y; v.w = unpk(zp[3]).y; }
                *(float4*)(sZ + (d0 + c) * 68 + m0) = v;
            }
        }
        __syncthreads();
    }
}

extern "C" void kernel_launch(void* const* d_in, const int* in_sizes, int n_in,
                              void* d_out, int out_size)
{
    (void)in_sizes; (void)n_in; (void)out_size;
    const float* z0     = (const float*)d_in[0];
    const float* ts     = (const float*)d_in[1];
    const float* dW     = (const float*)d_in[2];
    const float* W1     = (const float*)d_in[3];
    const float* b1     = (const float*)d_in[4];
    const float* W2     = (const float*)d_in[5];
    const float* b2     = (const float*)d_in[6];
    const float* W3     = (const float*)d_in[7];
    const float* b3     = (const float*)d_in[8];
    const float* logstd = (const float*)d_in[9];
    float* out = (float*)d_out;

    static bool attr_set = false;  // idempotent attribute; not a work guard
    if (!attr_set) {
        cudaFuncSetAttribute(sde_kernel,
                             cudaFuncAttributeMaxDynamicSharedMemorySize,
                             SMEM_FLOATS * sizeof(float));
        attr_set = true;
    }

    sde_kernel<<<BB / MT, 256, SMEM_FLOATS * sizeof(float)>>>(
        z0, ts, dW, W1, b1, W2, b2, W3, b3, logstd, out);
}

// round 11
// speedup vs baseline: 1.6054x; 1.6054x over previous
#include <cuda_runtime.h>
#include <math.h>
#include <stdint.h>

#define D   32
#define BB  8192
#define TT  256
#define MT  64      // rows per CTA -> 128 CTAs

// smem float offsets
#define SA1  0        // A1: z state [64][36]   (2304)
#define SH1  2304     // H1: [64][68]           (4352)
#define SH2  6656     // H2: [64][68]           (4352)
#define SW1  11008    // W1 rows1..32: [32][72] (2304)
#define SW2  13312    // W2: [64][72]           (4608)
#define SW3  17920    // W3: [64][40]           (2560)
#define STS_ 20480    // ts [256]
#define SMEM_FLOATS 20736

__device__ __forceinline__ uint32_t f2tf(float x){
    uint32_t r; asm("cvt.rna.tf32.f32 %0, %1;" : "=r"(r) : "f"(x)); return r;
}
__device__ __forceinline__ float tanha(float x){
    float y; asm("tanh.approx.f32 %0, %1;" : "=f"(y) : "f"(x)); return y;
}
__device__ __forceinline__ void mma8(float d[4],
    uint32_t a0, uint32_t a1, uint32_t a2, uint32_t a3,
    uint32_t b0, uint32_t b1){
    asm volatile("mma.sync.aligned.m16n8k8.row.col.f32.tf32.tf32.f32 "
        "{%0,%1,%2,%3}, {%4,%5,%6,%7}, {%8,%9}, {%0,%1,%2,%3};"
        : "+f"(d[0]), "+f"(d[1]), "+f"(d[2]), "+f"(d[3])
        : "r"(a0), "r"(a1), "r"(a2), "r"(a3), "r"(b0), "r"(b1));
}

// split fp32 -> (tf32 hi, tf32 lo)
#define SPLIT(x, hi, lo) { hi = f2tf(x); lo = f2tf((x) - __uint_as_float(hi)); }

__global__ __launch_bounds__(256, 1)
void sde_mma(const float* __restrict__ z0, const float* __restrict__ ts,
             const float* __restrict__ dW,
             const float* __restrict__ W1, const float* __restrict__ b1,
             const float* __restrict__ W2, const float* __restrict__ b2,
             const float* __restrict__ W3, const float* __restrict__ b3,
             const float* __restrict__ logstd, float* __restrict__ out)
{
    extern __shared__ float sm[];
    float* A1  = sm + SA1;
    float* H1  = sm + SH1;
    float* H2  = sm + SH2;
    float* W1s = sm + SW1;
    float* W2s = sm + SW2;
    float* W3s = sm + SW3;
    float* sTs = sm + STS_;

    const int tid  = threadIdx.x;
    const int w    = tid >> 5;
    const int lane = tid & 31;
    const int g    = lane >> 2;     // fragment row group 0..7
    const int tig  = lane & 3;      // thread-in-group 0..3
    const int mt   = w & 3;         // m16 tile index (rows)
    const int nh   = w >> 2;        // column half
    const int r0   = mt * 16 + g;   // fragment row (and r0+8)
    const int base = blockIdx.x * MT;

    // ---- staging ----
    for (int i = tid; i < 32*64; i += 256){ int k = i >> 6, n = i & 63; W1s[k*72 + n] = W1[(k+1)*64 + n]; }
    for (int i = tid; i < 64*64; i += 256){ int k = i >> 6, n = i & 63; W2s[k*72 + n] = W2[k*64 + n]; }
    for (int i = tid; i < 64*32; i += 256){ int k = i >> 5, n = i & 31; W3s[k*40 + n] = W3[k*32 + n]; }
    for (int i = tid; i < 64*32; i += 256){ int r = i >> 5, c = i & 31; A1[r*36 + c] = z0[(size_t)(base + r)*D + c]; }
    sTs[tid] = ts[tid];
    for (int i = tid; i < MT*D/2; i += 256)
        ((float2*)out)[(size_t)base*(D/2) + i] = ((const float2*)z0)[(size_t)base*(D/2) + i];

    // ---- hoisted per-thread constants (from gmem, once) ----
    float b1v[4][2], w10[4][2], b2v[4][2], b3v[2][2], sdv[2][2];
    #pragma unroll
    for (int nt = 0; nt < 4; nt++){
        int c = nh*32 + nt*8 + 2*tig;
        b1v[nt][0] = b1[c];  b1v[nt][1] = b1[c+1];
        w10[nt][0] = W1[c];  w10[nt][1] = W1[c+1];    // W1 row 0 (t-row)
        b2v[nt][0] = b2[c];  b2v[nt][1] = b2[c+1];
    }
    #pragma unroll
    for (int nt = 0; nt < 2; nt++){
        int c = nh*16 + nt*8 + 2*tig;
        b3v[nt][0] = b3[c];            b3v[nt][1] = b3[c+1];
        sdv[nt][0] = expf(logstd[c]);  sdv[nt][1] = expf(logstd[c+1]);
    }
    __syncthreads();

    // ==================== time loop ====================
    for (int t = 0; t < TT-1; ++t){
        const float tc  = sTs[t];
        const float dtv = sTs[t+1] - tc;
        const float sq  = sqrtf(dtv);

        // prefetch noise
        float2 dwv[2][2];
        #pragma unroll
        for (int nt = 0; nt < 2; nt++){
            int c = nh*16 + nt*8 + 2*tig;
            #pragma unroll
            for (int rp = 0; rp < 2; rp++)
                dwv[nt][rp] = *(const float2*)&dW[((size_t)t*BB + base + r0 + rp*8)*D + c];
        }

        // ---------- GEMM1: z @ W1[1:33]  (t folded into bias) ----------
        {
            float d1[4][4];
            #pragma unroll
            for (int nt = 0; nt < 4; nt++){
                float i0 = fmaf(tc, w10[nt][0], b1v[nt][0]);
                float i1 = fmaf(tc, w10[nt][1], b1v[nt][1]);
                d1[nt][0] = i0; d1[nt][1] = i1; d1[nt][2] = i0; d1[nt][3] = i1;
            }
            #pragma unroll
            for (int kt = 0; kt < 4; kt++){
                const float* ap = A1 + r0*36 + kt*8 + tig;
                float a0 = ap[0], a2 = ap[4], a1 = ap[8*36], a3 = ap[8*36 + 4];
                uint32_t ah0,ah1,ah2,ah3, al0,al1,al2,al3;
                SPLIT(a0, ah0, al0); SPLIT(a1, ah1, al1);
                SPLIT(a2, ah2, al2); SPLIT(a3, ah3, al3);
                #pragma unroll
                for (int nt = 0; nt < 4; nt++){
                    const float* bp = W1s + (kt*8 + tig)*72 + nh*32 + nt*8 + g;
                    float bb0 = bp[0], bb1 = bp[4*72];
                    uint32_t bh0,bh1, bl0,bl1;
                    SPLIT(bb0, bh0, bl0); SPLIT(bb1, bh1, bl1);
                    mma8(d1[nt], ah0,ah1,ah2,ah3, bh0,bh1);
                    mma8(d1[nt], ah0,ah1,ah2,ah3, bl0,bl1);
                    mma8(d1[nt], al0,al1,al2,al3, bh0,bh1);
                }
            }
            #pragma unroll
            for (int nt = 0; nt < 4; nt++){
                int c = nh*32 + nt*8 + 2*tig;
                float2 v0; v0.x = tanha(d1[nt][0]); v0.y = tanha(d1[nt][1]);
                float2 v1; v1.x = tanha(d1[nt][2]); v1.y = tanha(d1[nt][3]);
                *(float2*)&H1[r0*68 + c]       = v0;
                *(float2*)&H1[(r0+8)*68 + c]   = v1;
            }
        }
        __syncthreads();

        // ---------- GEMM2: h1 @ W2 ----------
        {
            float d2[4][4];
            #pragma unroll
            for (int nt = 0; nt < 4; nt++){
                d2[nt][0] = b2v[nt][0]; d2[nt][1] = b2v[nt][1];
                d2[nt][2] = b2v[nt][0]; d2[nt][3] = b2v[nt][1];
            }
            #pragma unroll
            for (int kt = 0; kt < 8; kt++){
                const float* ap = H1 + r0*68 + kt*8 + tig;
                float a0 = ap[0], a2 = ap[4], a1 = ap[8*68], a3 = ap[8*68 + 4];
                uint32_t ah0,ah1,ah2,ah3, al0,al1,al2,al3;
                SPLIT(a0, ah0, al0); SPLIT(a1, ah1, al1);
                SPLIT(a2, ah2, al2); SPLIT(a3, ah3, al3);
                #pragma unroll
                for (int nt = 0; nt < 4; nt++){
                    const float* bp = W2s + (kt*8 + tig)*72 + nh*32 + nt*8 + g;
                    float bb0 = bp[0], bb1 = bp[4*72];
                    uint32_t bh0,bh1, bl0,bl1;
                    SPLIT(bb0, bh0, bl0); SPLIT(bb1, bh1, bl1);
                    mma8(d2[nt], ah0,ah1,ah2,ah3, bh0,bh1);
                    mma8(d2[nt], ah0,ah1,ah2,ah3, bl0,bl1);
                    mma8(d2[nt], al0,al1,al2,al3, bh0,bh1);
                }
            }
            #pragma unroll
            for (int nt = 0; nt < 4; nt++){
                int c = nh*32 + nt*8 + 2*tig;
                float2 v0; v0.x = tanha(d2[nt][0]); v0.y = tanha(d2[nt][1]);
                float2 v1; v1.x = tanha(d2[nt][2]); v1.y = tanha(d2[nt][3]);
                *(float2*)&H2[r0*68 + c]       = v0;
                *(float2*)&H2[(r0+8)*68 + c]   = v1;
            }
        }
        __syncthreads();

        // ---------- GEMM3: h2 @ W3 + fused Euler-Maruyama ----------
        {
            float d3[2][4];
            #pragma unroll
            for (int nt = 0; nt < 2; nt++){
                d3[nt][0] = b3v[nt][0]; d3[nt][1] = b3v[nt][1];
                d3[nt][2] = b3v[nt][0]; d3[nt][3] = b3v[nt][1];
            }
            #pragma unroll
            for (int kt = 0; kt < 8; kt++){
                const float* ap = H2 + r0*68 + kt*8 + tig;
                float a0 = ap[0], a2 = ap[4], a1 = ap[8*68], a3 = ap[8*68 + 4];
                uint32_t ah0,ah1,ah2,ah3, al0,al1,al2,al3;
                SPLIT(a0, ah0, al0); SPLIT(a1, ah1, al1);
                SPLIT(a2, ah2, al2); SPLIT(a3, ah3, al3);
                #pragma unroll
                for (int nt = 0; nt < 2; nt++){
                    const float* bp = W3s + (kt*8 + tig)*40 + nh*16 + nt*8 + g;
                    float bb0 = bp[0], bb1 = bp[4*40];
                    uint32_t bh0,bh1, bl0,bl1;
                    SPLIT(bb0, bh0, bl0); SPLIT(bb1, bh1, bl1);
                    mma8(d3[nt], ah0,ah1,ah2,ah3, bh0,bh1);
                    mma8(d3[nt], ah0,ah1,ah2,ah3, bl0,bl1);
                    mma8(d3[nt], al0,al1,al2,al3, bh0,bh1);
                }
            }
            #pragma unroll
            for (int nt = 0; nt < 2; nt++){
                int c = nh*16 + nt*8 + 2*tig;
                float s0 = sdv[nt][0] * sq, s1 = sdv[nt][1] * sq;
                #pragma unroll
                for (int rp = 0; rp < 2; rp++){
                    int rr = r0 + rp*8;
                    float2 zo = *(float2*)&A1[rr*36 + c];
                    float2 zn;
                    zn.x = fmaf(d3[nt][rp*2 + 0], dtv, fmaf(s0, dwv[nt][rp].x, zo.x));
                    zn.y = fmaf(d3[nt][rp*2 + 1], dtv, fmaf(s1, dwv[nt][rp].y, zo.y));
                    *(float2*)&A1[rr*36 + c] = zn;
                    *(float2*)&out[((size_t)(t+1)*BB + base + rr)*D + c] = zn;
                }
            }
        }
        __syncthreads();
    }
}

extern "C" void kernel_launch(void* const* d_in, const int* in_sizes, int n_in,
                              void* d_out, int out_size)
{
    (void)in_sizes; (void)n_in; (void)out_size;
    const float* z0     = (const float*)d_in[0];
    const float* ts     = (const float*)d_in[1];
    const float* dW     = (const float*)d_in[2];
    const float* W1     = (const float*)d_in[3];
    const float* b1     = (const float*)d_in[4];
    const float* W2     = (const float*)d_in[5];
    const float* b2     = (const float*)d_in[6];
    const float* W3     = (const float*)d_in[7];
    const float* b3     = (const float*)d_in[8];
    const float* logstd = (const float*)d_in[9];
    float* out = (float*)d_out;

    static bool attr_set = false;  // idempotent attribute; not a work guard
    if (!attr_set) {
        cudaFuncSetAttribute(sde_mma, cudaFuncAttributeMaxDynamicSharedMemorySize,
                             SMEM_FLOATS * sizeof(float));
        attr_set = true;
    }

    sde_mma<<<BB / MT, 256, SMEM_FLOATS * sizeof(float)>>>(
        z0, ts, dW, W1, b1, W2, b2, W3, b3, logstd, out);
}

// round 12
// speedup vs baseline: 1.8115x; 1.1284x over previous
#include <cuda_runtime.h>
#include <math.h>
#include <stdint.h>

#define D   32
#define BB  8192
#define TT  256
#define MT  64      // rows per CTA -> 128 CTAs

// smem byte offsets
#define B_A1   0        // A1 z state fp32 [64][36]            9216
#define B_H1   9216     // H1 fp32 [64][68]                    17408
#define B_H2   26624    // H2 fp32 [64][68]                    17408
#define B_W1P  44032    // W1 rows1..32 pairs uint2 [32][68]   17408
#define B_W2P  61440    // W2 pairs uint2 [64][68]             34816
#define B_W3P  96256    // W3 pairs uint2 [64][36]             18432
#define B_TS   114688   // ts fp32 [256]                       1024
#define SMEM_BYTES 115712

__device__ __forceinline__ uint32_t f2tf(float x){
    uint32_t r; asm("cvt.rna.tf32.f32 %0, %1;" : "=r"(r) : "f"(x)); return r;
}
__device__ __forceinline__ float tanha(float x){
    float y; asm("tanh.approx.f32 %0, %1;" : "=f"(y) : "f"(x)); return y;
}
__device__ __forceinline__ void mma8(float d[4],
    uint32_t a0, uint32_t a1, uint32_t a2, uint32_t a3,
    uint32_t b0, uint32_t b1){
    asm volatile("mma.sync.aligned.m16n8k8.row.col.f32.tf32.tf32.f32 "
        "{%0,%1,%2,%3}, {%4,%5,%6,%7}, {%8,%9}, {%0,%1,%2,%3};"
        : "+f"(d[0]), "+f"(d[1]), "+f"(d[2]), "+f"(d[3])
        : "r"(a0), "r"(a1), "r"(a2), "r"(a3), "r"(b0), "r"(b1));
}

// split fp32 -> (tf32 hi, tf32 lo)
#define SPLIT(x, hi, lo) { hi = f2tf(x); lo = f2tf((x) - __uint_as_float(hi)); }

__global__ __launch_bounds__(256, 1)
void sde_mma(const float* __restrict__ z0, const float* __restrict__ ts,
             const float* __restrict__ dW,
             const float* __restrict__ W1, const float* __restrict__ b1,
             const float* __restrict__ W2, const float* __restrict__ b2,
             const float* __restrict__ W3, const float* __restrict__ b3,
             const float* __restrict__ logstd, float* __restrict__ out)
{
    extern __shared__ char smem[];
    float* A1  = (float*)(smem + B_A1);
    float* H1  = (float*)(smem + B_H1);
    float* H2  = (float*)(smem + B_H2);
    uint2* W1p = (uint2*)(smem + B_W1P);
    uint2* W2p = (uint2*)(smem + B_W2P);
    uint2* W3p = (uint2*)(smem + B_W3P);
    float* sTs = (float*)(smem + B_TS);

    const int tid  = threadIdx.x;
    const int w    = tid >> 5;
    const int lane = tid & 31;
    const int g    = lane >> 2;     // fragment row group 0..7
    const int tig  = lane & 3;      // thread-in-group 0..3
    const int mt   = w & 3;         // m16 tile index (rows)
    const int nh   = w >> 2;        // column half
    const int r0   = mt * 16 + g;   // fragment row (and r0+8)
    const int base = blockIdx.x * MT;

    // ---- staging: weights pre-split into tf32 (hi,lo) pairs ----
    for (int i = tid; i < 32*64; i += 256){
        int k = i >> 6, n = i & 63;
        float v = W1[(k+1)*64 + n];
        uint32_t hi, lo; SPLIT(v, hi, lo);
        W1p[k*68 + n] = make_uint2(hi, lo);
    }
    for (int i = tid; i < 64*64; i += 256){
        int k = i >> 6, n = i & 63;
        float v = W2[k*64 + n];
        uint32_t hi, lo; SPLIT(v, hi, lo);
        W2p[k*68 + n] = make_uint2(hi, lo);
    }
    for (int i = tid; i < 64*32; i += 256){
        int k = i >> 5, n = i & 31;
        float v = W3[k*32 + n];
        uint32_t hi, lo; SPLIT(v, hi, lo);
        W3p[k*36 + n] = make_uint2(hi, lo);
    }
    for (int i = tid; i < 64*32; i += 256){
        int r = i >> 5, c = i & 31;
        A1[r*36 + c] = z0[(size_t)(base + r)*D + c];
    }
    sTs[tid] = ts[tid];
    for (int i = tid; i < MT*D/2; i += 256)
        ((float2*)out)[(size_t)base*(D/2) + i] = ((const float2*)z0)[(size_t)base*(D/2) + i];

    // ---- hoisted per-thread constants (from gmem, once) ----
    float b1v[4][2], w10[4][2], b2v[4][2], b3v[2][2], sdv[2][2];
    #pragma unroll
    for (int nt = 0; nt < 4; nt++){
        int c = nh*32 + nt*8 + 2*tig;
        b1v[nt][0] = b1[c];  b1v[nt][1] = b1[c+1];
        w10[nt][0] = W1[c];  w10[nt][1] = W1[c+1];    // W1 row 0 (t-row)
        b2v[nt][0] = b2[c];  b2v[nt][1] = b2[c+1];
    }
    #pragma unroll
    for (int nt = 0; nt < 2; nt++){
        int c = nh*16 + nt*8 + 2*tig;
        b3v[nt][0] = b3[c];            b3v[nt][1] = b3[c+1];
        sdv[nt][0] = expf(logstd[c]);  sdv[nt][1] = expf(logstd[c+1]);
    }
    __syncthreads();

    // ==================== time loop ====================
    for (int t = 0; t < TT-1; ++t){
        const float tc  = sTs[t];
        const float dtv = sTs[t+1] - tc;
        const float sq  = sqrtf(dtv);

        // prefetch noise
        float2 dwv[2][2];
        #pragma unroll
        for (int nt = 0; nt < 2; nt++){
            int c = nh*16 + nt*8 + 2*tig;
            #pragma unroll
            for (int rp = 0; rp < 2; rp++)
                dwv[nt][rp] = *(const float2*)&dW[((size_t)t*BB + base + r0 + rp*8)*D + c];
        }

        // ---------- GEMM1: z @ W1[1:33]  (t folded into bias) ----------
        {
            float d1[4][4];
            #pragma unroll
            for (int nt = 0; nt < 4; nt++){
                float i0 = fmaf(tc, w10[nt][0], b1v[nt][0]);
                float i1 = fmaf(tc, w10[nt][1], b1v[nt][1]);
                d1[nt][0] = i0; d1[nt][1] = i1; d1[nt][2] = i0; d1[nt][3] = i1;
            }
            #pragma unroll
            for (int kt = 0; kt < 4; kt++){
                const float* ap = A1 + r0*36 + kt*8 + tig;
                float a0 = ap[0], a2 = ap[4], a1 = ap[8*36], a3 = ap[8*36 + 4];
                uint32_t ah0,ah1,ah2,ah3, al0,al1,al2,al3;
                SPLIT(a0, ah0, al0); SPLIT(a1, ah1, al1);
                SPLIT(a2, ah2, al2); SPLIT(a3, ah3, al3);
                #pragma unroll
                for (int nt = 0; nt < 4; nt++){
                    const uint2* bp = W1p + (kt*8 + tig)*68 + nh*32 + nt*8 + g;
                    uint2 p0 = bp[0], p1 = bp[4*68];
                    mma8(d1[nt], ah0,ah1,ah2,ah3, p0.x, p1.x);
                    mma8(d1[nt], ah0,ah1,ah2,ah3, p0.y, p1.y);
                    mma8(d1[nt], al0,al1,al2,al3, p0.x, p1.x);
                }
            }
            #pragma unroll
            for (int nt = 0; nt < 4; nt++){
                int c = nh*32 + nt*8 + 2*tig;
                float2 v0; v0.x = tanha(d1[nt][0]); v0.y = tanha(d1[nt][1]);
                float2 v1; v1.x = tanha(d1[nt][2]); v1.y = tanha(d1[nt][3]);
                *(float2*)&H1[r0*68 + c]       = v0;
                *(float2*)&H1[(r0+8)*68 + c]   = v1;
            }
        }
        __syncthreads();

        // ---------- GEMM2: h1 @ W2 ----------
        {
            float d2[4][4];
            #pragma unroll
            for (int nt = 0; nt < 4; nt++){
                d2[nt][0] = b2v[nt][0]; d2[nt][1] = b2v[nt][1];
                d2[nt][2] = b2v[nt][0]; d2[nt][3] = b2v[nt][1];
            }
            #pragma unroll
            for (int kt = 0; kt < 8; kt++){
                const float* ap = H1 + r0*68 + kt*8 + tig;
                float a0 = ap[0], a2 = ap[4], a1 = ap[8*68], a3 = ap[8*68 + 4];
                uint32_t ah0,ah1,ah2,ah3, al0,al1,al2,al3;
                SPLIT(a0, ah0, al0); SPLIT(a1, ah1, al1);
                SPLIT(a2, ah2, al2); SPLIT(a3, ah3, al3);
                #pragma unroll
                for (int nt = 0; nt < 4; nt++){
                    const uint2* bp = W2p + (kt*8 + tig)*68 + nh*32 + nt*8 + g;
                    uint2 p0 = bp[0], p1 = bp[4*68];
                    mma8(d2[nt], ah0,ah1,ah2,ah3, p0.x, p1.x);
                    mma8(d2[nt], ah0,ah1,ah2,ah3, p0.y, p1.y);
                    mma8(d2[nt], al0,al1,al2,al3, p0.x, p1.x);
                }
            }
            #pragma unroll
            for (int nt = 0; nt < 4; nt++){
                int c = nh*32 + nt*8 + 2*tig;
                float2 v0; v0.x = tanha(d2[nt][0]); v0.y = tanha(d2[nt][1]);
                float2 v1; v1.x = tanha(d2[nt][2]); v1.y = tanha(d2[nt][3]);
                *(float2*)&H2[r0*68 + c]       = v0;
                *(float2*)&H2[(r0+8)*68 + c]   = v1;
            }
        }
        __syncthreads();

        // ---------- GEMM3: h2 @ W3 + fused Euler-Maruyama ----------
        {
            float d3[2][4];
            #pragma unroll
            for (int nt = 0; nt < 2; nt++){
                d3[nt][0] = b3v[nt][0]; d3[nt][1] = b3v[nt][1];
                d3[nt][2] = b3v[nt][0]; d3[nt][3] = b3v[nt][1];
            }
            #pragma unroll
            for (int kt = 0; kt < 8; kt++){
                const float* ap = H2 + r0*68 + kt*8 + tig;
                float a0 = ap[0], a2 = ap[4], a1 = ap[8*68], a3 = ap[8*68 + 4];
                uint32_t ah0,ah1,ah2,ah3, al0,al1,al2,al3;
                SPLIT(a0, ah0, al0); SPLIT(a1, ah1, al1);
                SPLIT(a2, ah2, al2); SPLIT(a3, ah3, al3);
                #pragma unroll
                for (int nt = 0; nt < 2; nt++){
                    const uint2* bp = W3p + (kt*8 + tig)*36 + nh*16 + nt*8 + g;
                    uint2 p0 = bp[0], p1 = bp[4*36];
                    mma8(d3[nt], ah0,ah1,ah2,ah3, p0.x, p1.x);
                    mma8(d3[nt], ah0,ah1,ah2,ah3, p0.y, p1.y);
                    mma8(d3[nt], al0,al1,al2,al3, p0.x, p1.x);
                }
            }
            #pragma unroll
            for (int nt = 0; nt < 2; nt++){
                int c = nh*16 + nt*8 + 2*tig;
                float s0 = sdv[nt][0] * sq, s1 = sdv[nt][1] * sq;
                #pragma unroll
                for (int rp = 0; rp < 2; rp++){
                    int rr = r0 + rp*8;
                    float2 zo = *(float2*)&A1[rr*36 + c];
                    float2 zn;
                    zn.x = fmaf(d3[nt][rp*2 + 0], dtv, fmaf(s0, dwv[nt][rp].x, zo.x));
                    zn.y = fmaf(d3[nt][rp*2 + 1], dtv, fmaf(s1, dwv[nt][rp].y, zo.y));
                    *(float2*)&A1[rr*36 + c] = zn;
                    *(float2*)&out[((size_t)(t+1)*BB + base + rr)*D + c] = zn;
                }
            }
        }
        __syncthreads();
    }
}

extern "C" void kernel_launch(void* const* d_in, const int* in_sizes, int n_in,
                              void* d_out, int out_size)
{
    (void)in_sizes; (void)n_in; (void)out_size;
    const float* z0     = (const float*)d_in[0];
    const float* ts     = (const float*)d_in[1];
    const float* dW     = (const float*)d_in[2];
    const float* W1     = (const float*)d_in[3];
    const float* b1     = (const float*)d_in[4];
    const float* W2     = (const float*)d_in[5];
    const float* b2     = (const float*)d_in[6];
    const float* W3     = (const float*)d_in[7];
    const float* b3     = (const float*)d_in[8];
    const float* logstd = (const float*)d_in[9];
    float* out = (float*)d_out;

    static bool attr_set = false;  // idempotent attribute; not a work guard
    if (!attr_set) {
        cudaFuncSetAttribute(sde_mma, cudaFuncAttributeMaxDynamicSharedMemorySize,
                             SMEM_BYTES);
        attr_set = true;
    }

    sde_mma<<<BB / MT, 256, SMEM_BYTES>>>(
        z0, ts, dW, W1, b1, W2, b2, W3, b3, logstd, out);
}

// round 13
// speedup vs baseline: 2.5631x; 1.4149x over previous
#include <cuda_runtime.h>
#include <math.h>
#include <stdint.h>

#define D   32
#define BB  8192
#define TT  256
#define MT  64      // rows per CTA -> 128 CTAs

// smem byte offsets
#define B_A1   0        // A1 z state fp32 [64][36]            9216
#define B_H1   9216     // H1 fp32 [64][68]                    17408
#define B_H2   26624    // H2 fp32 [64][68]                    17408
#define B_W1P  44032    // W1 rows1..32 pairs uint2 [32][68]   17408
#define B_W2P  61440    // W2 pairs uint2 [64][68]             34816
#define B_W3P  96256    // W3 pairs uint2 [64][36]             18432
#define B_TS   114688   // ts fp32 [256]                       1024
#define SMEM_BYTES 115712

__device__ __forceinline__ uint32_t f2tf(float x){
    uint32_t r; asm("cvt.rna.tf32.f32 %0, %1;" : "=r"(r) : "f"(x)); return r;
}
__device__ __forceinline__ float tanha(float x){
    float y; asm("tanh.approx.f32 %0, %1;" : "=f"(y) : "f"(x)); return y;
}
__device__ __forceinline__ void mma8(float d[4],
    uint32_t a0, uint32_t a1, uint32_t a2, uint32_t a3,
    uint32_t b0, uint32_t b1){
    asm volatile("mma.sync.aligned.m16n8k8.row.col.f32.tf32.tf32.f32 "
        "{%0,%1,%2,%3}, {%4,%5,%6,%7}, {%8,%9}, {%0,%1,%2,%3};"
        : "+f"(d[0]), "+f"(d[1]), "+f"(d[2]), "+f"(d[3])
        : "r"(a0), "r"(a1), "r"(a2), "r"(a3), "r"(b0), "r"(b1));
}

// full split for weights (staged once)
#define SPLIT(x, hi, lo) { hi = f2tf(x); lo = f2tf((x) - __uint_as_float(hi)); }

__global__ __launch_bounds__(256, 1)
void sde_mma(const float* __restrict__ z0, const float* __restrict__ ts,
             const float* __restrict__ dW,
             const float* __restrict__ W1, const float* __restrict__ b1,
             const float* __restrict__ W2, const float* __restrict__ b2,
             const float* __restrict__ W3, const float* __restrict__ b3,
             const float* __restrict__ logstd, float* __restrict__ out)
{
    extern __shared__ char smem[];
    float* A1  = (float*)(smem + B_A1);
    float* H1  = (float*)(smem + B_H1);
    float* H2  = (float*)(smem + B_H2);
    uint2* W1p = (uint2*)(smem + B_W1P);
    uint2* W2p = (uint2*)(smem + B_W2P);
    uint2* W3p = (uint2*)(smem + B_W3P);
    float* sTs = (float*)(smem + B_TS);

    const int tid  = threadIdx.x;
    const int w    = tid >> 5;
    const int lane = tid & 31;
    const int g    = lane >> 2;     // fragment row group 0..7
    const int tig  = lane & 3;      // thread-in-group 0..3
    const int mt   = w & 3;         // m16 tile index (rows)
    const int nh   = w >> 2;        // column half
    const int r0   = mt * 16 + g;   // fragment row (and r0+8)
    const int base = blockIdx.x * MT;

    // ---- staging: weights pre-split into tf32 (hi,lo) pairs ----
    for (int i = tid; i < 32*64; i += 256){
        int k = i >> 6, n = i & 63;
        float v = W1[(k+1)*64 + n];
        uint32_t hi, lo; SPLIT(v, hi, lo);
        W1p[k*68 + n] = make_uint2(hi, lo);
    }
    for (int i = tid; i < 64*64; i += 256){
        int k = i >> 6, n = i & 63;
        float v = W2[k*64 + n];
        uint32_t hi, lo; SPLIT(v, hi, lo);
        W2p[k*68 + n] = make_uint2(hi, lo);
    }
    for (int i = tid; i < 64*32; i += 256){
        int k = i >> 5, n = i & 31;
        float v = W3[k*32 + n];
        uint32_t hi, lo; SPLIT(v, hi, lo);
        W3p[k*36 + n] = make_uint2(hi, lo);
    }
    for (int i = tid; i < 64*32; i += 256){
        int r = i >> 5, c = i & 31;
        A1[r*36 + c] = z0[(size_t)(base + r)*D + c];
    }
    sTs[tid] = ts[tid];
    for (int i = tid; i < MT*D/2; i += 256)
        ((float2*)out)[(size_t)base*(D/2) + i] = ((const float2*)z0)[(size_t)base*(D/2) + i];

    // ---- hoisted per-thread constants (from gmem, once) ----
    float b1v[4][2], w10[4][2], b2v[4][2], b3v[2][2], sdv[2][2];
    #pragma unroll
    for (int nt = 0; nt < 4; nt++){
        int c = nh*32 + nt*8 + 2*tig;
        b1v[nt][0] = b1[c];  b1v[nt][1] = b1[c+1];
        w10[nt][0] = W1[c];  w10[nt][1] = W1[c+1];    // W1 row 0 (t-row)
        b2v[nt][0] = b2[c];  b2v[nt][1] = b2[c+1];
    }
    #pragma unroll
    for (int nt = 0; nt < 2; nt++){
        int c = nh*16 + nt*8 + 2*tig;
        b3v[nt][0] = b3[c];            b3v[nt][1] = b3[c+1];
        sdv[nt][0] = expf(logstd[c]);  sdv[nt][1] = expf(logstd[c+1]);
    }
    __syncthreads();

    // ==================== time loop ====================
    for (int t = 0; t < TT-1; ++t){
        const float tc  = sTs[t];
        const float dtv = sTs[t+1] - tc;
        const float sq  = sqrtf(dtv);

        // prefetch noise
        float2 dwv[2][2];
        #pragma unroll
        for (int nt = 0; nt < 2; nt++){
            int c = nh*16 + nt*8 + 2*tig;
            #pragma unroll
            for (int rp = 0; rp < 2; rp++)
                dwv[nt][rp] = *(const float2*)&dW[((size_t)t*BB + base + r0 + rp*8)*D + c];
        }

        // ---------- GEMM1: z @ W1[1:33]  (t folded into bias) ----------
        {
            float d1[4][4];
            #pragma unroll
            for (int nt = 0; nt < 4; nt++){
                float i0 = fmaf(tc, w10[nt][0], b1v[nt][0]);
                float i1 = fmaf(tc, w10[nt][1], b1v[nt][1]);
                d1[nt][0] = i0; d1[nt][1] = i1; d1[nt][2] = i0; d1[nt][3] = i1;
            }
            #pragma unroll
            for (int kt = 0; kt < 4; kt++){
                const float* ap = A1 + r0*36 + kt*8 + tig;
                uint32_t ah0 = f2tf(ap[0]), ah2 = f2tf(ap[4]);
                uint32_t ah1 = f2tf(ap[8*36]), ah3 = f2tf(ap[8*36 + 4]);
                #pragma unroll
                for (int nt = 0; nt < 4; nt++){
                    const uint2* bp = W1p + (kt*8 + tig)*68 + nh*32 + nt*8 + g;
                    uint2 p0 = bp[0], p1 = bp[4*68];
                    mma8(d1[nt], ah0,ah1,ah2,ah3, p0.x, p1.x);
                    mma8(d1[nt], ah0,ah1,ah2,ah3, p0.y, p1.y);
                }
            }
            #pragma unroll
            for (int nt = 0; nt < 4; nt++){
                int c = nh*32 + nt*8 + 2*tig;
                float2 v0; v0.x = tanha(d1[nt][0]); v0.y = tanha(d1[nt][1]);
                float2 v1; v1.x = tanha(d1[nt][2]); v1.y = tanha(d1[nt][3]);
                *(float2*)&H1[r0*68 + c]       = v0;
                *(float2*)&H1[(r0+8)*68 + c]   = v1;
            }
        }
        __syncthreads();

        // ---------- GEMM2: h1 @ W2 ----------
        {
            float d2[4][4];
            #pragma unroll
            for (int nt = 0; nt < 4; nt++){
                d2[nt][0] = b2v[nt][0]; d2[nt][1] = b2v[nt][1];
                d2[nt][2] = b2v[nt][0]; d2[nt][3] = b2v[nt][1];
            }
            #pragma unroll
            for (int kt = 0; kt < 8; kt++){
                const float* ap = H1 + r0*68 + kt*8 + tig;
                uint32_t ah0 = f2tf(ap[0]), ah2 = f2tf(ap[4]);
                uint32_t ah1 = f2tf(ap[8*68]), ah3 = f2tf(ap[8*68 + 4]);
                #pragma unroll
                for (int nt = 0; nt < 4; nt++){
                    const uint2* bp = W2p + (kt*8 + tig)*68 + nh*32 + nt*8 + g;
                    uint2 p0 = bp[0], p1 = bp[4*68];
                    mma8(d2[nt], ah0,ah1,ah2,ah3, p0.x, p1.x);
                    mma8(d2[nt], ah0,ah1,ah2,ah3, p0.y, p1.y);
                }
            }
            #pragma unroll
            for (int nt = 0; nt < 4; nt++){
                int c = nh*32 + nt*8 + 2*tig;
                float2 v0; v0.x = tanha(d2[nt][0]); v0.y = tanha(d2[nt][1]);
                float2 v1; v1.x = tanha(d2[nt][2]); v1.y = tanha(d2[nt][3]);
                *(float2*)&H2[r0*68 + c]       = v0;
                *(float2*)&H2[(r0+8)*68 + c]   = v1;
            }
        }
        __syncthreads();

        // ---------- GEMM3: h2 @ W3 + fused Euler-Maruyama ----------
        {
            float d3[2][4];
            #pragma unroll
            for (int nt = 0; nt < 2; nt++){
                d3[nt][0] = b3v[nt][0]; d3[nt][1] = b3v[nt][1];
                d3[nt][2] = b3v[nt][0]; d3[nt][3] = b3v[nt][1];
            }
            #pragma unroll
            for (int kt = 0; kt < 8; kt++){
                const float* ap = H2 + r0*68 + kt*8 + tig;
                uint32_t ah0 = f2tf(ap[0]), ah2 = f2tf(ap[4]);
                uint32_t ah1 = f2tf(ap[8*68]), ah3 = f2tf(ap[8*68 + 4]);
                #pragma unroll
                for (int nt = 0; nt < 2; nt++){
                    const uint2* bp = W3p + (kt*8 + tig)*36 + nh*16 + nt*8 + g;
                    uint2 p0 = bp[0], p1 = bp[4*36];
                    mma8(d3[nt], ah0,ah1,ah2,ah3, p0.x, p1.x);
                    mma8(d3[nt], ah0,ah1,ah2,ah3, p0.y, p1.y);
                }
            }
            #pragma unroll
            for (int nt = 0; nt < 2; nt++){
                int c = nh*16 + nt*8 + 2*tig;
                float s0 = sdv[nt][0] * sq, s1 = sdv[nt][1] * sq;
                #pragma unroll
                for (int rp = 0; rp < 2; rp++){
                    int rr = r0 + rp*8;
                    float2 zo = *(float2*)&A1[rr*36 + c];
                    float2 zn;
                    zn.x = fmaf(d3[nt][rp*2 + 0], dtv, fmaf(s0, dwv[nt][rp].x, zo.x));
                    zn.y = fmaf(d3[nt][rp*2 + 1], dtv, fmaf(s1, dwv[nt][rp].y, zo.y));
                    *(float2*)&A1[rr*36 + c] = zn;
                    *(float2*)&out[((size_t)(t+1)*BB + base + rr)*D + c] = zn;
                }
            }
        }
        __syncthreads();
    }
}

extern "C" void kernel_launch(void* const* d_in, const int* in_sizes, int n_in,
                              void* d_out, int out_size)
{
    (void)in_sizes; (void)n_in; (void)out_size;
    const float* z0     = (const float*)d_in[0];
    const float* ts     = (const float*)d_in[1];
    const float* dW     = (const float*)d_in[2];
    const float* W1     = (const float*)d_in[3];
    const float* b1     = (const float*)d_in[4];
    const float* W2     = (const float*)d_in[5];
    const float* b2     = (const float*)d_in[6];
    const float* W3     = (const float*)d_in[7];
    const float* b3     = (const float*)d_in[8];
    const float* logstd = (const float*)d_in[9];
    float* out = (float*)d_out;

    static bool attr_set = false;  // idempotent attribute; not a work guard
    if (!attr_set) {
        cudaFuncSetAttribute(sde_mma, cudaFuncAttributeMaxDynamicSharedMemorySize,
                             SMEM_BYTES);
        attr_set = true;
    }

    sde_mma<<<BB / MT, 256, SMEM_BYTES>>>(
        z0, ts, dW, W1, b1, W2, b2, W3, b3, logstd, out);
}